// round 1
// baseline (speedup 1.0000x reference)
#include <cuda_runtime.h>
#include <cuda_bf16.h>

// Problem constants (from reference setup_inputs)
#define BS        8
#define RDIM      256
#define NBLK      (BS * RDIM)      // 2048 independent graph blocks
#define NODES     64
#define MROWS     (NBLK * NODES)   // 131072
#define ENC       31
#define FIN       32               // 1 + enc
#define HEADS     8
#define HID       64
#define OUTC      32
#define HC12      (HEADS * HID)    // 512
#define HC3       (HEADS * OUTC)   // 256
#define NEG_SLOPE 0.2f

// -------- device scratch (alloc-free rule: __device__ globals) --------
__device__ float g_x0[(size_t)MROWS * FIN];          // 16 MB
__device__ float g_bufA[(size_t)MROWS * HC12];       // 256 MB
__device__ float g_bufB[(size_t)MROWS * HC12];       // 256 MB

// ---------------------------------------------------------------------
// Build x0 = concat(xs[..., None], broadcast pos_enc) : [MROWS, 32]
// xs: [8,256,64] (flat index == m), pos_enc: [8,64,31]
// ---------------------------------------------------------------------
__global__ void build_x0_kernel(const float* __restrict__ xs,
                                const float* __restrict__ pos_enc) {
    int idx = blockIdx.x * blockDim.x + threadIdx.x;   // over MROWS*FIN
    if (idx >= MROWS * FIN) return;
    int m = idx / FIN;
    int f = idx % FIN;
    float v;
    if (f == 0) {
        v = xs[m];
    } else {
        int b = m / (RDIM * NODES);
        int n = m % NODES;
        v = pos_enc[(b * NODES + n) * ENC + (f - 1)];
    }
    g_x0[idx] = v;
}

// ---------------------------------------------------------------------
// Simple SIMT GEMM: C[M,N] = A[M,K] * B[K,N], all row-major fp32.
// BM=BN=64, BK=16, 256 threads, 4x4 microtile. M,N,K multiples of tile.
// ---------------------------------------------------------------------
#define BM 64
#define BN 64
#define BK 16
__global__ __launch_bounds__(256) void gemm_kernel(
    const float* __restrict__ A, const float* __restrict__ B,
    float* __restrict__ C, int M, int N, int K) {
    __shared__ float As[BK][BM + 1];
    __shared__ float Bs[BK][BN + 1];
    const int tid = threadIdx.x;
    const int tx = tid % 16;          // 16 cols of threads
    const int ty = tid / 16;          // 16 rows of threads
    const int row0 = blockIdx.y * BM;
    const int col0 = blockIdx.x * BN;

    float acc[4][4] = {};

    for (int k0 = 0; k0 < K; k0 += BK) {
        // load A tile (BM x BK) into As[k][m]
        #pragma unroll
        for (int idx = tid; idx < BM * BK; idx += 256) {
            int m = idx / BK;
            int k = idx % BK;
            As[k][m] = A[(size_t)(row0 + m) * K + k0 + k];
        }
        // load B tile (BK x BN) into Bs[k][n]
        #pragma unroll
        for (int idx = tid; idx < BK * BN; idx += 256) {
            int k = idx / BN;
            int n = idx % BN;
            Bs[k][n] = B[(size_t)(k0 + k) * N + col0 + n];
        }
        __syncthreads();
        #pragma unroll
        for (int k = 0; k < BK; k++) {
            float a[4], b[4];
            #pragma unroll
            for (int i = 0; i < 4; i++) a[i] = As[k][ty * 4 + i];
            #pragma unroll
            for (int j = 0; j < 4; j++) b[j] = Bs[k][tx * 4 + j];
            #pragma unroll
            for (int i = 0; i < 4; i++)
                #pragma unroll
                for (int j = 0; j < 4; j++)
                    acc[i][j] += a[i] * b[j];
        }
        __syncthreads();
    }
    #pragma unroll
    for (int i = 0; i < 4; i++)
        #pragma unroll
        for (int j = 0; j < 4; j++)
            C[(size_t)(row0 + ty * 4 + i) * N + col0 + tx * 4 + j] = acc[i][j];
}

// ---------------------------------------------------------------------
// GAT attention for one (graph-block g, head hd).
// in/out: [MROWS, HC] row-major. h = in[g*64 .. g*64+63][hd*C .. hd*C+C-1]
// logits[i][j] = leaky_relu(ld[i] + ls[j]); softmax over j; out = P @ h + bias
// 256 threads. C is 64 or 32.
// ---------------------------------------------------------------------
__global__ __launch_bounds__(256) void attn_kernel(
    const float* __restrict__ in, float* __restrict__ out,
    const float* __restrict__ a_src, const float* __restrict__ a_dst,
    const float* __restrict__ bias, int C, int HC) {
    __shared__ float sh_h[NODES * HID];   // up to 64*64 fp32 = 16KB
    __shared__ float sh_p[NODES * NODES]; // 16KB
    __shared__ float sh_ls[NODES];
    __shared__ float sh_ld[NODES];
    __shared__ float sh_as[HID];
    __shared__ float sh_ad[HID];

    const int g  = blockIdx.y;
    const int hd = blockIdx.x;
    const int tid = threadIdx.x;
    const size_t base = (size_t)g * NODES * HC + hd * C;

    // load h tile [64, C] and attention vectors
    for (int idx = tid; idx < NODES * C; idx += 256) {
        int n = idx / C;
        int c = idx % C;
        sh_h[idx] = in[base + (size_t)n * HC + c];
    }
    if (tid < C) {
        sh_as[tid] = a_src[hd * C + tid];
        sh_ad[tid] = a_dst[hd * C + tid];
    }
    __syncthreads();

    // per-node alpha_src / alpha_dst (64 threads)
    if (tid < NODES) {
        float ls = 0.f, ld = 0.f;
        const float* hp = &sh_h[tid * C];
        for (int c = 0; c < C; c++) {
            float hv = hp[c];
            ls += hv * sh_as[c];
            ld += hv * sh_ad[c];
        }
        sh_ls[tid] = ls;
        sh_ld[tid] = ld;
    }
    __syncthreads();

    // softmax rows: thread i handles row i (64 threads)
    if (tid < NODES) {
        const float ldi = sh_ld[tid];
        float mx = -1e30f;
        #pragma unroll 4
        for (int j = 0; j < NODES; j++) {
            float v = ldi + sh_ls[j];
            v = (v > 0.f) ? v : NEG_SLOPE * v;
            sh_p[tid * NODES + j] = v;
            mx = fmaxf(mx, v);
        }
        float s = 0.f;
        #pragma unroll 4
        for (int j = 0; j < NODES; j++) {
            float e = __expf(sh_p[tid * NODES + j] - mx);
            sh_p[tid * NODES + j] = e;
            s += e;
        }
        float inv = 1.f / s;
        #pragma unroll 4
        for (int j = 0; j < NODES; j++)
            sh_p[tid * NODES + j] *= inv;
    }
    __syncthreads();

    // out[i][c] = sum_j P[i][j] * h[j][c]
    // thread: i = tid/4, covers C/4 contiguous columns
    const int i  = tid >> 2;
    const int cg = tid & 3;
    const int cw = C >> 2;            // 16 or 8
    const int cbase = cg * cw;
    float accv[16];
    #pragma unroll
    for (int k = 0; k < 16; k++) accv[k] = 0.f;

    const float* prow = &sh_p[i * NODES];
    for (int j = 0; j < NODES; j++) {
        float p = prow[j];
        const float* hrow = &sh_h[j * C + cbase];
        #pragma unroll
        for (int k = 0; k < 16; k++)
            if (k < cw) accv[k] += p * hrow[k];
    }
    float* orow = &out[base + (size_t)i * HC + cbase];
    #pragma unroll
    for (int k = 0; k < 16; k++)
        if (k < cw) orow[k] = accv[k] + bias[hd * C + cbase + k];
}

// ---------------------------------------------------------------------
// Mean over nodes: out[g, hc] = mean_n y3[(g*64+n), hc], HC3=256
// ---------------------------------------------------------------------
__global__ void mean_kernel(const float* __restrict__ y,
                            float* __restrict__ out) {
    int idx = blockIdx.x * blockDim.x + threadIdx.x;   // over NBLK*HC3
    if (idx >= NBLK * HC3) return;
    int g  = idx / HC3;
    int hc = idx % HC3;
    float s = 0.f;
    const float* p = y + (size_t)g * NODES * HC3 + hc;
    #pragma unroll 8
    for (int n = 0; n < NODES; n++)
        s += p[(size_t)n * HC3];
    out[idx] = s * (1.0f / NODES);
}

// ---------------------------------------------------------------------
extern "C" void kernel_launch(void* const* d_in, const int* in_sizes, int n_in,
                              void* d_out, int out_size) {
    const float* xs      = (const float*)d_in[0];
    const float* pos_enc = (const float*)d_in[1];
    const float* W1  = (const float*)d_in[2];
    const float* as1 = (const float*)d_in[3];
    const float* ad1 = (const float*)d_in[4];
    const float* b1  = (const float*)d_in[5];
    const float* W2  = (const float*)d_in[6];
    const float* as2 = (const float*)d_in[7];
    const float* ad2 = (const float*)d_in[8];
    const float* b2  = (const float*)d_in[9];
    const float* W3  = (const float*)d_in[10];
    const float* as3 = (const float*)d_in[11];
    const float* ad3 = (const float*)d_in[12];
    const float* b3  = (const float*)d_in[13];
    float* out = (float*)d_out;

    float *x0, *bufA, *bufB;
    cudaGetSymbolAddress((void**)&x0,   g_x0);
    cudaGetSymbolAddress((void**)&bufA, g_bufA);
    cudaGetSymbolAddress((void**)&bufB, g_bufB);

    // 1) build x0
    {
        int total = MROWS * FIN;
        build_x0_kernel<<<(total + 255) / 256, 256>>>(xs, pos_enc);
    }

    dim3 attn_grid(HEADS, NBLK);

    // 2) h1 = x0 @ W1   [131072,512]
    gemm_kernel<<<dim3(HC12 / BN, MROWS / BM), 256>>>(x0, W1, bufA, MROWS, HC12, FIN);
    // 3) y1 = attn(h1)
    attn_kernel<<<attn_grid, 256>>>(bufA, bufB, as1, ad1, b1, HID, HC12);
    // 4) h2 = y1 @ W2
    gemm_kernel<<<dim3(HC12 / BN, MROWS / BM), 256>>>(bufB, W2, bufA, MROWS, HC12, HC12);
    // 5) y2 = attn(h2)
    attn_kernel<<<attn_grid, 256>>>(bufA, bufB, as2, ad2, b2, HID, HC12);
    // 6) h3 = y2 @ W3   [131072,256]
    gemm_kernel<<<dim3(HC3 / BN, MROWS / BM), 256>>>(bufB, W3, bufA, MROWS, HC3, HC12);
    // 7) y3 = attn(h3)
    attn_kernel<<<attn_grid, 256>>>(bufA, bufB, as3, ad3, b3, OUTC, HC3);
    // 8) mean over nodes -> out [2048, 256]
    {
        int total = NBLK * HC3;
        mean_kernel<<<(total + 255) / 256, 256>>>(bufB, out);
    }
}

// round 2
// speedup vs baseline: 2.3887x; 2.3887x over previous
#include <cuda_runtime.h>
#include <cuda_bf16.h>

// Problem constants (from reference setup_inputs)
#define BS        8
#define RDIM      256
#define NBLK      (BS * RDIM)      // 2048 independent graph blocks
#define NODES     64
#define MROWS     (NBLK * NODES)   // 131072
#define ENC       31
#define FIN       32               // 1 + enc
#define HEADS     8
#define HID       64
#define OUTC      32
#define HC12      (HEADS * HID)    // 512
#define HC3       (HEADS * OUTC)   // 256
#define NEG_SLOPE 0.2f

typedef unsigned long long ull;

// ---- packed fp32x2 helpers (sm_103a dual-FP32 path, PTX-only) ----
__device__ __forceinline__ ull pack2(float x, float y) {
    ull r; asm("mov.b64 %0, {%1, %2};" : "=l"(r) : "f"(x), "f"(y)); return r;
}
__device__ __forceinline__ ull fma2(ull a, ull b, ull c) {
    ull d; asm("fma.rn.f32x2 %0, %1, %2, %3;" : "=l"(d) : "l"(a), "l"(b), "l"(c)); return d;
}
__device__ __forceinline__ float2 unpack2(ull v) {
    float2 f; asm("mov.b64 {%0, %1}, %2;" : "=f"(f.x), "=f"(f.y) : "l"(v)); return f;
}

// -------- device scratch (alloc-free rule: __device__ globals) --------
__device__ float g_x0[(size_t)MROWS * FIN];          // 16 MB
__device__ float g_bufA[(size_t)MROWS * HC12];       // 256 MB
__device__ float g_bufB[(size_t)MROWS * HC12];       // 256 MB

// ---------------------------------------------------------------------
// Build x0 = concat(xs[..., None], broadcast pos_enc) : [MROWS, 32]
// ---------------------------------------------------------------------
__global__ void build_x0_kernel(const float* __restrict__ xs,
                                const float* __restrict__ pos_enc) {
    int idx = blockIdx.x * blockDim.x + threadIdx.x;   // over MROWS*FIN
    if (idx >= MROWS * FIN) return;
    int m = idx / FIN;
    int f = idx % FIN;
    float v;
    if (f == 0) {
        v = xs[m];
    } else {
        int b = m / (RDIM * NODES);
        int n = m % NODES;
        v = pos_enc[(b * NODES + n) * ENC + (f - 1)];
    }
    g_x0[idx] = v;
}

// ---------------------------------------------------------------------
// SGEMM with packed f32x2 FMA: C[M,N] = A[M,K] * B[K,N], row-major fp32.
// BM=128, BN=64, BK=16, 256 threads, 8x4 microtile (as 8x2 f32x2 pairs).
// M % 128 == 0, N % 64 == 0, K % 16 == 0.
// ---------------------------------------------------------------------
#define BM 128
#define BN 64
#define BKK 16
__global__ __launch_bounds__(256) void gemm_kernel(
    const float* __restrict__ A, const float* __restrict__ B,
    float* __restrict__ C, int M, int N, int K) {
    __shared__ float As[BKK][BM + 4];   // pad 4: 16B-aligned rows, low STS conflicts
    __shared__ float Bs[BKK][BN];

    const int tid = threadIdx.x;
    const int tx = tid & 15;            // n-dir: 16 threads * 4 cols
    const int ty = tid >> 4;            // m-dir: 16 threads * 8 rows
    const int row0 = blockIdx.y * BM;
    const int col0 = blockIdx.x * BN;

    // global load mapping
    const int ar = tid >> 2;            // 0..63
    const int ak = (tid & 3) << 2;      // 0,4,8,12
    const float* Aptr  = A + (size_t)(row0 + ar) * K + ak;
    const float* Aptr2 = Aptr + (size_t)64 * K;
    const int bk = tid >> 4;            // 0..15
    const int bn = tx << 2;
    const float* Bptr = B + (size_t)bk * N + col0 + bn;

    ull acc[8][2];
    #pragma unroll
    for (int i = 0; i < 8; i++) { acc[i][0] = 0ull; acc[i][1] = 0ull; }

    float4 av0 = *(const float4*)Aptr;
    float4 av1 = *(const float4*)Aptr2;
    float4 bv  = *(const float4*)Bptr;

    for (int k0 = 0; k0 < K; k0 += BKK) {
        // stage to shared (A transposed)
        As[ak + 0][ar] = av0.x; As[ak + 1][ar] = av0.y;
        As[ak + 2][ar] = av0.z; As[ak + 3][ar] = av0.w;
        As[ak + 0][ar + 64] = av1.x; As[ak + 1][ar + 64] = av1.y;
        As[ak + 2][ar + 64] = av1.z; As[ak + 3][ar + 64] = av1.w;
        *(float4*)&Bs[bk][bn] = bv;
        __syncthreads();

        if (k0 + BKK < K) {     // prefetch next chunk
            av0 = *(const float4*)(Aptr + k0 + BKK);
            av1 = *(const float4*)(Aptr2 + k0 + BKK);
            bv  = *(const float4*)(Bptr + (size_t)(k0 + BKK) * N);
        }

        #pragma unroll
        for (int k = 0; k < BKK; k++) {
            float4 a0 = *(const float4*)&As[k][ty * 8];
            float4 a1 = *(const float4*)&As[k][ty * 8 + 4];
            ulonglong2 b2v = *(const ulonglong2*)&Bs[k][tx * 4];
            float am[8] = {a0.x, a0.y, a0.z, a0.w, a1.x, a1.y, a1.z, a1.w};
            #pragma unroll
            for (int i = 0; i < 8; i++) {
                ull ad = pack2(am[i], am[i]);
                acc[i][0] = fma2(ad, b2v.x, acc[i][0]);
                acc[i][1] = fma2(ad, b2v.y, acc[i][1]);
            }
        }
        __syncthreads();
    }

    // epilogue
    #pragma unroll
    for (int i = 0; i < 8; i++) {
        float2 c0 = unpack2(acc[i][0]);
        float2 c1 = unpack2(acc[i][1]);
        float4 v = make_float4(c0.x, c0.y, c1.x, c1.y);
        *(float4*)(C + (size_t)(row0 + ty * 8 + i) * N + col0 + tx * 4) = v;
    }
}

// ---------------------------------------------------------------------
// GAT attention for one (graph-block g, head hd). Templated on C.
// logits[i][j] = leaky_relu(ld[i] + ls[j]); softmax over j; out = P @ h + b
// ---------------------------------------------------------------------
template<int C, int HC>
__global__ __launch_bounds__(256) void attn_kernel(
    const float* __restrict__ in, float* __restrict__ out,
    const float* __restrict__ a_src, const float* __restrict__ a_dst,
    const float* __restrict__ bias) {
    __shared__ float sh_h[NODES * C];
    __shared__ float sh_p[NODES * 65];   // pad 65: conflict-free row broadcast
    __shared__ float sh_ls[NODES];
    __shared__ float sh_ld[NODES];
    __shared__ float sh_as[C];
    __shared__ float sh_ad[C];

    const int g   = blockIdx.y;
    const int hd  = blockIdx.x;
    const int tid = threadIdx.x;
    const int lane = tid & 31;
    const int warp = tid >> 5;
    const size_t base = (size_t)g * NODES * HC + hd * C;

    // ---- load h tile [64, C] (float4, coalesced) + attention vectors ----
    #pragma unroll
    for (int idx = tid; idx < NODES * C / 4; idx += 256) {
        int n  = idx / (C / 4);
        int c4 = idx % (C / 4);
        *(float4*)&sh_h[n * C + c4 * 4] =
            *(const float4*)(in + base + (size_t)n * HC + c4 * 4);
    }
    if (tid < C) {
        sh_as[tid] = a_src[hd * C + tid];
        sh_ad[tid] = a_dst[hd * C + tid];
    }
    __syncthreads();

    // ---- per-node ls/ld: 4 threads per node, shfl-reduce ----
    {
        const int n = tid >> 2;
        const int q = tid & 3;
        const int CW = C / 4;
        float ls = 0.f, ld = 0.f;
        const float* hp = &sh_h[n * C + q * CW];
        #pragma unroll
        for (int k = 0; k < CW; k++) {
            float hv = hp[k];
            ls += hv * sh_as[q * CW + k];
            ld += hv * sh_ad[q * CW + k];
        }
        ls += __shfl_down_sync(0xffffffffu, ls, 2, 4);
        ls += __shfl_down_sync(0xffffffffu, ls, 1, 4);
        ld += __shfl_down_sync(0xffffffffu, ld, 2, 4);
        ld += __shfl_down_sync(0xffffffffu, ld, 1, 4);
        if (q == 0) { sh_ls[n] = ls; sh_ld[n] = ld; }
    }
    __syncthreads();

    // ---- softmax rows: warp per row, lane covers j=lane and j=lane+32 ----
    {
        const float ls0 = sh_ls[lane];
        const float ls1 = sh_ls[lane + 32];
        for (int i = warp; i < NODES; i += 8) {
            const float ldi = sh_ld[i];
            float v0 = ldi + ls0;
            float v1 = ldi + ls1;
            v0 = (v0 > 0.f) ? v0 : NEG_SLOPE * v0;
            v1 = (v1 > 0.f) ? v1 : NEG_SLOPE * v1;
            float mx = fmaxf(v0, v1);
            #pragma unroll
            for (int o = 16; o > 0; o >>= 1)
                mx = fmaxf(mx, __shfl_xor_sync(0xffffffffu, mx, o));
            float e0 = __expf(v0 - mx);
            float e1 = __expf(v1 - mx);
            float s = e0 + e1;
            #pragma unroll
            for (int o = 16; o > 0; o >>= 1)
                s += __shfl_xor_sync(0xffffffffu, s, o);
            float inv = 1.f / s;
            sh_p[i * 65 + lane]      = e0 * inv;
            sh_p[i * 65 + lane + 32] = e1 * inv;
        }
    }
    __syncthreads();

    // ---- out[i][c] = sum_j P[i][j] h[j][c], packed f32x2 ----
    {
        const int i = tid >> 2;
        const int q = tid & 3;
        const int CW = C / 4;          // 16 or 8
        ull acc[CW / 2];
        #pragma unroll
        for (int t = 0; t < CW / 2; t++) acc[t] = 0ull;

        const float* prow = &sh_p[i * 65];
        #pragma unroll 4
        for (int j = 0; j < NODES; j++) {
            float p = prow[j];
            ull pp = pack2(p, p);
            const ulonglong2* hrow = (const ulonglong2*)(sh_h + j * C + q * CW);
            #pragma unroll
            for (int t = 0; t < CW / 4; t++) {
                ulonglong2 hv = hrow[t];
                acc[2 * t]     = fma2(pp, hv.x, acc[2 * t]);
                acc[2 * t + 1] = fma2(pp, hv.y, acc[2 * t + 1]);
            }
        }

        float ob[CW];
        #pragma unroll
        for (int t = 0; t < CW / 2; t++) {
            float2 f = unpack2(acc[t]);
            ob[2 * t] = f.x; ob[2 * t + 1] = f.y;
        }
        float* orow = out + base + (size_t)i * HC + q * CW;
        const float* bp = bias + hd * C + q * CW;
        #pragma unroll
        for (int k = 0; k < CW; k += 4) {
            float4 v = make_float4(ob[k] + bp[k], ob[k + 1] + bp[k + 1],
                                   ob[k + 2] + bp[k + 2], ob[k + 3] + bp[k + 3]);
            *(float4*)(orow + k) = v;
        }
    }
}

// ---------------------------------------------------------------------
// Mean over nodes: out[g, hc] = mean_n y3[(g*64+n), hc], HC3=256
// ---------------------------------------------------------------------
__global__ void mean_kernel(const float* __restrict__ y,
                            float* __restrict__ out) {
    int idx = blockIdx.x * blockDim.x + threadIdx.x;   // over NBLK*HC3
    if (idx >= NBLK * HC3) return;
    int g  = idx / HC3;
    int hc = idx % HC3;
    float s = 0.f;
    const float* p = y + (size_t)g * NODES * HC3 + hc;
    #pragma unroll 8
    for (int n = 0; n < NODES; n++)
        s += p[(size_t)n * HC3];
    out[idx] = s * (1.0f / NODES);
}

// ---------------------------------------------------------------------
extern "C" void kernel_launch(void* const* d_in, const int* in_sizes, int n_in,
                              void* d_out, int out_size) {
    const float* xs      = (const float*)d_in[0];
    const float* pos_enc = (const float*)d_in[1];
    const float* W1  = (const float*)d_in[2];
    const float* as1 = (const float*)d_in[3];
    const float* ad1 = (const float*)d_in[4];
    const float* b1  = (const float*)d_in[5];
    const float* W2  = (const float*)d_in[6];
    const float* as2 = (const float*)d_in[7];
    const float* ad2 = (const float*)d_in[8];
    const float* b2  = (const float*)d_in[9];
    const float* W3  = (const float*)d_in[10];
    const float* as3 = (const float*)d_in[11];
    const float* ad3 = (const float*)d_in[12];
    const float* b3  = (const float*)d_in[13];
    float* out = (float*)d_out;

    float *x0, *bufA, *bufB;
    cudaGetSymbolAddress((void**)&x0,   g_x0);
    cudaGetSymbolAddress((void**)&bufA, g_bufA);
    cudaGetSymbolAddress((void**)&bufB, g_bufB);

    // 1) build x0
    {
        int total = MROWS * FIN;
        build_x0_kernel<<<(total + 255) / 256, 256>>>(xs, pos_enc);
    }

    dim3 attn_grid(HEADS, NBLK);

    // 2) h1 = x0 @ W1   [131072,512]
    gemm_kernel<<<dim3(HC12 / BN, MROWS / BM), 256>>>(x0, W1, bufA, MROWS, HC12, FIN);
    // 3) y1 = attn(h1)
    attn_kernel<HID, HC12><<<attn_grid, 256>>>(bufA, bufB, as1, ad1, b1);
    // 4) h2 = y1 @ W2
    gemm_kernel<<<dim3(HC12 / BN, MROWS / BM), 256>>>(bufB, W2, bufA, MROWS, HC12, HC12);
    // 5) y2 = attn(h2)
    attn_kernel<HID, HC12><<<attn_grid, 256>>>(bufA, bufB, as2, ad2, b2);
    // 6) h3 = y2 @ W3   [131072,256]
    gemm_kernel<<<dim3(HC3 / BN, MROWS / BM), 256>>>(bufB, W3, bufA, MROWS, HC3, HC12);
    // 7) y3 = attn(h3)
    attn_kernel<OUTC, HC3><<<attn_grid, 256>>>(bufA, bufB, as3, ad3, b3);
    // 8) mean over nodes -> out [2048, 256]
    {
        int total = NBLK * HC3;
        mean_kernel<<<(total + 255) / 256, 256>>>(bufB, out);
    }
}

// round 4
// speedup vs baseline: 2.5674x; 1.0748x over previous
#include <cuda_runtime.h>
#include <cuda_bf16.h>
#include <cstdint>

// Problem constants
#define BS        8
#define RDIM      256
#define NBLK      (BS * RDIM)      // 2048
#define NODES     64
#define MROWS     (NBLK * NODES)   // 131072
#define ENC       31
#define FIN       32
#define HEADS     8
#define HID       64
#define OUTC      32
#define HC12      (HEADS * HID)    // 512
#define HC3       (HEADS * OUTC)   // 256
#define NEG_SLOPE 0.2f

typedef unsigned long long ull;
typedef __nv_bfloat16 bf16;

// ---------------- packed fp32x2 helpers (attention) ----------------
__device__ __forceinline__ ull pack2(float x, float y) {
    ull r; asm("mov.b64 %0, {%1, %2};" : "=l"(r) : "f"(x), "f"(y)); return r;
}
__device__ __forceinline__ ull fma2(ull a, ull b, ull c) {
    ull d; asm("fma.rn.f32x2 %0, %1, %2, %3;" : "=l"(d) : "l"(a), "l"(b), "l"(c)); return d;
}
__device__ __forceinline__ float2 unpack2(ull v) {
    float2 f; asm("mov.b64 {%0, %1}, %2;" : "=f"(f.x), "=f"(f.y) : "l"(v)); return f;
}

__device__ __forceinline__ uint32_t smem_u32(const void* p) {
    uint32_t a;
    asm("{ .reg .u64 t; cvta.to.shared.u64 t, %1; cvt.u32.u64 %0, t; }" : "=r"(a) : "l"(p));
    return a;
}

// ---------------- mma.sync / ldmatrix helpers (arch-generic tensor path) ----
__device__ __forceinline__ void ldsm4(uint32_t* r, uint32_t addr) {
    asm volatile("ldmatrix.sync.aligned.m8n8.x4.shared.b16 {%0,%1,%2,%3}, [%4];"
        : "=r"(r[0]), "=r"(r[1]), "=r"(r[2]), "=r"(r[3]) : "r"(addr));
}
__device__ __forceinline__ void mma16816(float* d, const uint32_t* a, const uint32_t* b) {
    asm volatile(
        "mma.sync.aligned.m16n8k16.row.col.f32.bf16.bf16.f32 "
        "{%0,%1,%2,%3}, {%4,%5,%6,%7}, {%8,%9}, {%0,%1,%2,%3};"
        : "+f"(d[0]), "+f"(d[1]), "+f"(d[2]), "+f"(d[3])
        : "r"(a[0]), "r"(a[1]), "r"(a[2]), "r"(a[3]), "r"(b[0]), "r"(b[1]));
}

// ---------------- device scratch ----------------
__device__ float g_bufA[(size_t)MROWS * HC12];       // 256 MB (h, fp32)
__device__ float g_bufB[(size_t)MROWS * HC3];        // 128 MB (y3, fp32)
__device__ bf16  g_acth[(size_t)MROWS * HC12];       // activations hi
__device__ bf16  g_actl[(size_t)MROWS * HC12];       // activations lo
__device__ bf16  g_w1h[512 * 64],  g_w1l[512 * 64];
__device__ bf16  g_w2h[512 * 512], g_w2l[512 * 512];
__device__ bf16  g_w3h[256 * 512], g_w3l[256 * 512];

// ---------------- prep kernels ----------------
__global__ void build_x0_split(const float* __restrict__ xs,
                               const float* __restrict__ pos_enc,
                               bf16* __restrict__ ah, bf16* __restrict__ al) {
    int idx = blockIdx.x * blockDim.x + threadIdx.x;   // MROWS*64
    if (idx >= MROWS * 64) return;
    int m = idx >> 6;
    int f = idx & 63;
    float v = 0.f;
    if (f == 0) v = xs[m];
    else if (f < FIN) {
        int b = m / (RDIM * NODES);
        int n = m % NODES;
        v = pos_enc[(b * NODES + n) * ENC + (f - 1)];
    }
    bf16 h = __float2bfloat16(v);
    ah[idx] = h;
    al[idx] = __float2bfloat16(v - __bfloat162float(h));
}

// W [Ksrc, N] -> Wt_hi/lo [N, Kpad] (transposed, zero-padded, split)
__global__ void prep_w(const float* __restrict__ W, bf16* __restrict__ th,
                       bf16* __restrict__ tl, int Ksrc, int N, int Kpad) {
    int idx = blockIdx.x * blockDim.x + threadIdx.x;
    if (idx >= N * Kpad) return;
    int n = idx / Kpad, k = idx % Kpad;
    float v = (k < Ksrc) ? W[(size_t)k * N + n] : 0.f;
    bf16 h = __float2bfloat16(v);
    th[idx] = h;
    tl[idx] = __float2bfloat16(v - __bfloat162float(h));
}

// ---------------- HMMA GEMM (split-bf16 x3) ----------------
// C[128 x 64 tile] = A[M,K] @ Wt^T, Wt stored [N,K] K-major. K % 32 == 0.
// Block: 256 thr, 8 warps (4m x 2n), warp tile 32x32, mma m16n8k16.
// smem tiles: A 128x32 (hi,lo), B 64x32 (hi,lo); 16B-chunk XOR swizzle.
#define STS_OFF(row, c) ((row) * 64 + (((c) ^ ((row) & 3)) << 4))

template<int K>
__global__ __launch_bounds__(256) void gemm_mma(
    const bf16* __restrict__ Ah, const bf16* __restrict__ Al,
    const bf16* __restrict__ Bh, const bf16* __restrict__ Bl,
    float* __restrict__ C, int Ntot) {
    __shared__ __align__(16) char sAh[128 * 64];   // 128 rows x 64B
    __shared__ __align__(16) char sAl[128 * 64];
    __shared__ __align__(16) char sBh[64 * 64];    // 64 rows x 64B
    __shared__ __align__(16) char sBl[64 * 64];

    const int tid  = threadIdx.x;
    const int wid  = tid >> 5;
    const int lane = tid & 31;
    const int row0 = blockIdx.y * 128;
    const int col0 = blockIdx.x * 64;
    constexpr int T = K / 32;

    // global->smem mapping (16B chunks)
    const int arow0 = tid >> 2;              // A chunk 0: rows 0..63
    const int ac    = tid & 3;
    const int arow1 = arow0 + 64;            // A chunk 1: rows 64..127
    const int brow  = tid >> 2;              // B: rows 0..63
    const uint32_t a_sts0 = STS_OFF(arow0, ac);
    const uint32_t a_sts1 = STS_OFF(arow1, ac);
    const uint32_t b_sts  = STS_OFF(brow, ac);

    const bf16* gAh0 = Ah + (size_t)(row0 + arow0) * K + ac * 8;
    const bf16* gAh1 = Ah + (size_t)(row0 + arow1) * K + ac * 8;
    const bf16* gAl0 = Al + (size_t)(row0 + arow0) * K + ac * 8;
    const bf16* gAl1 = Al + (size_t)(row0 + arow1) * K + ac * 8;
    const bf16* gBh  = Bh + (size_t)(col0 + brow) * K + ac * 8;
    const bf16* gBl  = Bl + (size_t)(col0 + brow) * K + ac * 8;

    // warp compute mapping
    const int mr = (wid & 3) * 32;
    const int nb = (wid >> 2) * 32;
    const uint32_t sAh_b = smem_u32(sAh);
    const uint32_t sAl_b = smem_u32(sAl);
    const uint32_t sBh_b = smem_u32(sBh);
    const uint32_t sBl_b = smem_u32(sBl);

    // ldmatrix lane address components
    const int rowlA = (lane & 7) + ((lane >> 3) & 1) * 8;   // A x4: m0/m1 rows, m2/m3 same
    const int chA   = (lane >> 4);                          // chunk +0/+1
    const int rowlB = (lane & 7) + (lane >> 4) * 8;         // B x4: m0/m1 n0-7, m2/m3 n8-15
    const int chB   = (lane >> 3) & 1;
    const int lx3   = lane & 3;

    float acc[2][4][4];
    #pragma unroll
    for (int i = 0; i < 2; i++)
        #pragma unroll
        for (int j = 0; j < 4; j++)
            #pragma unroll
            for (int q = 0; q < 4; q++) acc[i][j][q] = 0.f;

    uint4 pa0h = *(const uint4*)gAh0;
    uint4 pa1h = *(const uint4*)gAh1;
    uint4 pa0l = *(const uint4*)gAl0;
    uint4 pa1l = *(const uint4*)gAl1;
    uint4 pbh  = *(const uint4*)gBh;
    uint4 pbl  = *(const uint4*)gBl;

    for (int t = 0; t < T; t++) {
        *(uint4*)(sAh + a_sts0) = pa0h;
        *(uint4*)(sAh + a_sts1) = pa1h;
        *(uint4*)(sAl + a_sts0) = pa0l;
        *(uint4*)(sAl + a_sts1) = pa1l;
        *(uint4*)(sBh + b_sts)  = pbh;
        *(uint4*)(sBl + b_sts)  = pbl;
        __syncthreads();

        if (t + 1 < T) {
            int ko = (t + 1) * 32;
            pa0h = *(const uint4*)(gAh0 + ko);
            pa1h = *(const uint4*)(gAh1 + ko);
            pa0l = *(const uint4*)(gAl0 + ko);
            pa1l = *(const uint4*)(gAl1 + ko);
            pbh  = *(const uint4*)(gBh + ko);
            pbl  = *(const uint4*)(gBl + ko);
        }

        #pragma unroll
        for (int kk = 0; kk < 2; kk++) {       // two k16 steps in BK=32
            const int c0 = kk * 2;
            uint32_t fAh[2][4], fAl[2][4], fBh[2][4], fBl[2][4];
            #pragma unroll
            for (int sm = 0; sm < 2; sm++) {
                int r = mr + sm * 16 + rowlA;
                uint32_t off = r * 64 + (((c0 + chA) ^ lx3) << 4);
                ldsm4(fAh[sm], sAh_b + off);
                ldsm4(fAl[sm], sAl_b + off);
            }
            #pragma unroll
            for (int tp = 0; tp < 2; tp++) {
                int r = nb + tp * 16 + rowlB;
                uint32_t off = r * 64 + (((c0 + chB) ^ lx3) << 4);
                ldsm4(fBh[tp], sBh_b + off);
                ldsm4(fBl[tp], sBl_b + off);
            }
            #pragma unroll
            for (int sm = 0; sm < 2; sm++) {
                #pragma unroll
                for (int tn = 0; tn < 4; tn++) {
                    const int tp = tn >> 1, hf = (tn & 1) * 2;
                    const uint32_t bh[2] = {fBh[tp][hf], fBh[tp][hf + 1]};
                    const uint32_t bl[2] = {fBl[tp][hf], fBl[tp][hf + 1]};
                    mma16816(acc[sm][tn], fAh[sm], bh);
                    mma16816(acc[sm][tn], fAl[sm], bh);
                    mma16816(acc[sm][tn], fAh[sm], bl);
                }
            }
        }
        __syncthreads();
    }

    // epilogue: C fragment rows gid, gid+8; cols tig*2
    const int gid = lane >> 2;
    const int tig = lane & 3;
    #pragma unroll
    for (int sm = 0; sm < 2; sm++) {
        #pragma unroll
        for (int tn = 0; tn < 4; tn++) {
            int r = row0 + mr + sm * 16 + gid;
            int c = col0 + nb + tn * 8 + tig * 2;
            *(float2*)(C + (size_t)r * Ntot + c) =
                make_float2(acc[sm][tn][0], acc[sm][tn][1]);
            *(float2*)(C + (size_t)(r + 8) * Ntot + c) =
                make_float2(acc[sm][tn][2], acc[sm][tn][3]);
        }
    }
}

// ---------------- GAT attention ----------------
// OMODE 0: write fp32 to out; OMODE 1: write split bf16 to oh/ol
template<int C, int HC, int OMODE>
__global__ __launch_bounds__(256) void attn_kernel(
    const float* __restrict__ in, float* __restrict__ out,
    bf16* __restrict__ oh, bf16* __restrict__ ol,
    const float* __restrict__ a_src, const float* __restrict__ a_dst,
    const float* __restrict__ bias) {
    __shared__ float sh_h[NODES * C];
    __shared__ float sh_p[NODES * 65];
    __shared__ float sh_ls[NODES];
    __shared__ float sh_ld[NODES];
    __shared__ float sh_as[C];
    __shared__ float sh_ad[C];

    const int g   = blockIdx.y;
    const int hd  = blockIdx.x;
    const int tid = threadIdx.x;
    const int lane = tid & 31;
    const int warp = tid >> 5;
    const size_t base = (size_t)g * NODES * HC + hd * C;

    #pragma unroll
    for (int idx = tid; idx < NODES * C / 4; idx += 256) {
        int n  = idx / (C / 4);
        int c4 = idx % (C / 4);
        *(float4*)&sh_h[n * C + c4 * 4] =
            *(const float4*)(in + base + (size_t)n * HC + c4 * 4);
    }
    if (tid < C) {
        sh_as[tid] = a_src[hd * C + tid];
        sh_ad[tid] = a_dst[hd * C + tid];
    }
    __syncthreads();

    {   // per-node ls/ld
        const int n = tid >> 2;
        const int q = tid & 3;
        const int CW = C / 4;
        float ls = 0.f, ld = 0.f;
        const float* hp = &sh_h[n * C + q * CW];
        #pragma unroll
        for (int k = 0; k < CW; k++) {
            float hv = hp[k];
            ls += hv * sh_as[q * CW + k];
            ld += hv * sh_ad[q * CW + k];
        }
        ls += __shfl_down_sync(0xffffffffu, ls, 2, 4);
        ls += __shfl_down_sync(0xffffffffu, ls, 1, 4);
        ld += __shfl_down_sync(0xffffffffu, ld, 2, 4);
        ld += __shfl_down_sync(0xffffffffu, ld, 1, 4);
        if (q == 0) { sh_ls[n] = ls; sh_ld[n] = ld; }
    }
    __syncthreads();

    {   // softmax: warp per row
        const float ls0 = sh_ls[lane];
        const float ls1 = sh_ls[lane + 32];
        for (int i = warp; i < NODES; i += 8) {
            const float ldi = sh_ld[i];
            float v0 = ldi + ls0;
            float v1 = ldi + ls1;
            v0 = (v0 > 0.f) ? v0 : NEG_SLOPE * v0;
            v1 = (v1 > 0.f) ? v1 : NEG_SLOPE * v1;
            float mx = fmaxf(v0, v1);
            #pragma unroll
            for (int o = 16; o > 0; o >>= 1)
                mx = fmaxf(mx, __shfl_xor_sync(0xffffffffu, mx, o));
            float e0 = __expf(v0 - mx);
            float e1 = __expf(v1 - mx);
            float s = e0 + e1;
            #pragma unroll
            for (int o = 16; o > 0; o >>= 1)
                s += __shfl_xor_sync(0xffffffffu, s, o);
            float inv = 1.f / s;
            sh_p[i * 65 + lane]      = e0 * inv;
            sh_p[i * 65 + lane + 32] = e1 * inv;
        }
    }
    __syncthreads();

    {   // out[i][c] = sum_j P[i][j] h[j][c]
        const int i = tid >> 2;
        const int q = tid & 3;
        const int CW = C / 4;
        ull acc[CW / 2];
        #pragma unroll
        for (int t = 0; t < CW / 2; t++) acc[t] = 0ull;

        const float* prow = &sh_p[i * 65];
        #pragma unroll 4
        for (int j = 0; j < NODES; j++) {
            float p = prow[j];
            ull pp = pack2(p, p);
            const ulonglong2* hrow = (const ulonglong2*)(sh_h + j * C + q * CW);
            #pragma unroll
            for (int t = 0; t < CW / 4; t++) {
                ulonglong2 hv = hrow[t];
                acc[2 * t]     = fma2(pp, hv.x, acc[2 * t]);
                acc[2 * t + 1] = fma2(pp, hv.y, acc[2 * t + 1]);
            }
        }

        float ob[CW];
        #pragma unroll
        for (int t = 0; t < CW / 2; t++) {
            float2 f = unpack2(acc[t]);
            ob[2 * t] = f.x; ob[2 * t + 1] = f.y;
        }
        const float* bp = bias + hd * C + q * CW;
        if (OMODE == 0) {
            float* orow = out + base + (size_t)i * HC + q * CW;
            #pragma unroll
            for (int k = 0; k < CW; k += 4) {
                float4 v = make_float4(ob[k] + bp[k], ob[k + 1] + bp[k + 1],
                                       ob[k + 2] + bp[k + 2], ob[k + 3] + bp[k + 3]);
                *(float4*)(orow + k) = v;
            }
        } else {
            size_t ob0 = base + (size_t)i * HC + q * CW;
            #pragma unroll
            for (int k = 0; k < CW; k++) {
                float v = ob[k] + bp[k];
                bf16 h = __float2bfloat16(v);
                oh[ob0 + k] = h;
                ol[ob0 + k] = __float2bfloat16(v - __bfloat162float(h));
            }
        }
    }
}

// ---------------- mean over nodes ----------------
__global__ void mean_kernel(const float* __restrict__ y, float* __restrict__ out) {
    int idx = blockIdx.x * blockDim.x + threadIdx.x;   // NBLK*HC3
    if (idx >= NBLK * HC3) return;
    int g  = idx / HC3;
    int hc = idx % HC3;
    float s = 0.f;
    const float* p = y + (size_t)g * NODES * HC3 + hc;
    #pragma unroll 8
    for (int n = 0; n < NODES; n++)
        s += p[(size_t)n * HC3];
    out[idx] = s * (1.0f / NODES);
}

// ---------------------------------------------------------------------
extern "C" void kernel_launch(void* const* d_in, const int* in_sizes, int n_in,
                              void* d_out, int out_size) {
    const float* xs      = (const float*)d_in[0];
    const float* pos_enc = (const float*)d_in[1];
    const float* W1  = (const float*)d_in[2];
    const float* as1 = (const float*)d_in[3];
    const float* ad1 = (const float*)d_in[4];
    const float* b1  = (const float*)d_in[5];
    const float* W2  = (const float*)d_in[6];
    const float* as2 = (const float*)d_in[7];
    const float* ad2 = (const float*)d_in[8];
    const float* b2  = (const float*)d_in[9];
    const float* W3  = (const float*)d_in[10];
    const float* as3 = (const float*)d_in[11];
    const float* ad3 = (const float*)d_in[12];
    const float* b3  = (const float*)d_in[13];
    float* out = (float*)d_out;

    float *bufA, *bufB;
    bf16 *acth, *actl, *w1h, *w1l, *w2h, *w2l, *w3h, *w3l;
    cudaGetSymbolAddress((void**)&bufA, g_bufA);
    cudaGetSymbolAddress((void**)&bufB, g_bufB);
    cudaGetSymbolAddress((void**)&acth, g_acth);
    cudaGetSymbolAddress((void**)&actl, g_actl);
    cudaGetSymbolAddress((void**)&w1h, g_w1h);
    cudaGetSymbolAddress((void**)&w1l, g_w1l);
    cudaGetSymbolAddress((void**)&w2h, g_w2h);
    cudaGetSymbolAddress((void**)&w2l, g_w2l);
    cudaGetSymbolAddress((void**)&w3h, g_w3h);
    cudaGetSymbolAddress((void**)&w3l, g_w3l);

    // prep
    build_x0_split<<<(MROWS * 64 + 255) / 256, 256>>>(xs, pos_enc, acth, actl);
    prep_w<<<(512 * 64 + 255) / 256, 256>>>(W1, w1h, w1l, FIN, HC12, 64);
    prep_w<<<(512 * 512 + 255) / 256, 256>>>(W2, w2h, w2l, HC12, HC12, 512);
    prep_w<<<(256 * 512 + 255) / 256, 256>>>(W3, w3h, w3l, HC12, HC3, 512);

    dim3 attn_grid(HEADS, NBLK);

    // layer 1
    gemm_mma<64><<<dim3(HC12 / 64, MROWS / 128), 256>>>(
        acth, actl, w1h, w1l, bufA, HC12);
    attn_kernel<HID, HC12, 1><<<attn_grid, 256>>>(
        bufA, nullptr, acth, actl, as1, ad1, b1);
    // layer 2
    gemm_mma<512><<<dim3(HC12 / 64, MROWS / 128), 256>>>(
        acth, actl, w2h, w2l, bufA, HC12);
    attn_kernel<HID, HC12, 1><<<attn_grid, 256>>>(
        bufA, nullptr, acth, actl, as2, ad2, b2);
    // layer 3
    gemm_mma<512><<<dim3(HC3 / 64, MROWS / 128), 256>>>(
        acth, actl, w3h, w3l, bufA, HC3);
    attn_kernel<OUTC, HC3, 0><<<attn_grid, 256>>>(
        bufA, bufB, nullptr, nullptr, as3, ad3, b3);
    // mean
    mean_kernel<<<(NBLK * HC3 + 255) / 256, 256>>>(bufB, out);
}

// round 5
// speedup vs baseline: 4.5161x; 1.7590x over previous
#include <cuda_runtime.h>
#include <cuda_bf16.h>
#include <cstdint>

// Problem constants
#define BS        8
#define RDIM      256
#define NBLK      (BS * RDIM)      // 2048
#define NODES     64
#define MROWS     (NBLK * NODES)   // 131072
#define ENC       31
#define FIN       32
#define HEADS     8
#define HID       64
#define OUTC      32
#define HC12      (HEADS * HID)    // 512
#define HC3       (HEADS * OUTC)   // 256
#define NEG_SLOPE 0.2f

typedef unsigned long long ull;
typedef __nv_bfloat16 bf16;

// ---------------- packed fp32x2 helpers ----------------
__device__ __forceinline__ ull pack2(float x, float y) {
    ull r; asm("mov.b64 %0, {%1, %2};" : "=l"(r) : "f"(x), "f"(y)); return r;
}
__device__ __forceinline__ ull fma2(ull a, ull b, ull c) {
    ull d; asm("fma.rn.f32x2 %0, %1, %2, %3;" : "=l"(d) : "l"(a), "l"(b), "l"(c)); return d;
}
__device__ __forceinline__ float2 unpack2(ull v) {
    float2 f; asm("mov.b64 {%0, %1}, %2;" : "=f"(f.x), "=f"(f.y) : "l"(v)); return f;
}
__device__ __forceinline__ uint32_t smem_u32(const void* p) {
    uint32_t a;
    asm("{ .reg .u64 t; cvta.to.shared.u64 t, %1; cvt.u32.u64 %0, t; }" : "=r"(a) : "l"(p));
    return a;
}

// ---------------- mma.sync / ldmatrix (arch-generic tensor path) ----
__device__ __forceinline__ void ldsm4(uint32_t* r, uint32_t addr) {
    asm volatile("ldmatrix.sync.aligned.m8n8.x4.shared.b16 {%0,%1,%2,%3}, [%4];"
        : "=r"(r[0]), "=r"(r[1]), "=r"(r[2]), "=r"(r[3]) : "r"(addr));
}
__device__ __forceinline__ void mma16816(float* d, const uint32_t* a, const uint32_t* b) {
    asm volatile(
        "mma.sync.aligned.m16n8k16.row.col.f32.bf16.bf16.f32 "
        "{%0,%1,%2,%3}, {%4,%5,%6,%7}, {%8,%9}, {%0,%1,%2,%3};"
        : "+f"(d[0]), "+f"(d[1]), "+f"(d[2]), "+f"(d[3])
        : "r"(a[0]), "r"(a[1]), "r"(a[2]), "r"(a[3]), "r"(b[0]), "r"(b[1]));
}

// ---------------- device scratch ----------------
__device__ bf16 g_a0h[(size_t)MROWS * 64],  g_a0l[(size_t)MROWS * 64];    // x0 split
__device__ bf16 g_a1h[(size_t)MROWS * HC12], g_a1l[(size_t)MROWS * HC12];
__device__ bf16 g_a2h[(size_t)MROWS * HC12], g_a2l[(size_t)MROWS * HC12];
__device__ bf16 g_w1h[512 * 64],  g_w1l[512 * 64];
__device__ bf16 g_w2h[512 * 512], g_w2l[512 * 512];
__device__ bf16 g_w3h[256 * 512], g_w3l[256 * 512];

// ---------------- prep kernels ----------------
__global__ void build_x0_split(const float* __restrict__ xs,
                               const float* __restrict__ pos_enc,
                               bf16* __restrict__ ah, bf16* __restrict__ al) {
    int idx = blockIdx.x * blockDim.x + threadIdx.x;   // MROWS*64
    if (idx >= MROWS * 64) return;
    int m = idx >> 6;
    int f = idx & 63;
    float v = 0.f;
    if (f == 0) v = xs[m];
    else if (f < FIN) {
        int b = m / (RDIM * NODES);
        int n = m % NODES;
        v = pos_enc[(b * NODES + n) * ENC + (f - 1)];
    }
    bf16 h = __float2bfloat16(v);
    ah[idx] = h;
    al[idx] = __float2bfloat16(v - __bfloat162float(h));
}

// W [Ksrc, N] -> Wt_hi/lo [N, Kpad] (transposed, zero-padded, split)
__global__ void prep_w(const float* __restrict__ W, bf16* __restrict__ th,
                       bf16* __restrict__ tl, int Ksrc, int N, int Kpad) {
    int idx = blockIdx.x * blockDim.x + threadIdx.x;
    if (idx >= N * Kpad) return;
    int n = idx / Kpad, k = idx % Kpad;
    float v = (k < Ksrc) ? W[(size_t)k * N + n] : 0.f;
    bf16 h = __float2bfloat16(v);
    th[idx] = h;
    tl[idx] = __float2bfloat16(v - __bfloat162float(h));
}

// ---------------- fused GEMM (split-bf16 x3 HMMA) + GAT attention ----------------
// Tile: 128 rows (= 2 graph blocks) x 64 cols (= 64/CH heads).
// GEMM mainloop identical structure to R3 but with fixed conflict-free swizzle.
// Epilogue: C tile -> smem -> ls/ld -> softmax -> AV -> split-bf16 out (OMODE1)
// or node-mean -> outmean (OMODE0, layer 3).
// Swizzle: 64B rows, key = (row>>1)&3 -> conflict-free STS.128 and LDSM phases.
#define STS_OFF(row, c) ((row) * 64 + ((((c) ^ (((row) >> 1) & 3))) << 4))

template<int K, int CH, int OMODE>
__global__ __launch_bounds__(256) void gemm_attn(
    const bf16* __restrict__ Ah, const bf16* __restrict__ Al,
    const bf16* __restrict__ Bh, const bf16* __restrict__ Bl,
    const float* __restrict__ a_src, const float* __restrict__ a_dst,
    const float* __restrict__ bias,
    bf16* __restrict__ oh, bf16* __restrict__ ol,
    float* __restrict__ outmean) {
    constexpr int HPT = 64 / CH;     // heads per tile
    constexpr int U   = 2 * HPT;     // attention units per CTA
    constexpr int TU  = 256 / U;     // threads per unit (128 or 64)
    constexpr int T   = K / 32;

    extern __shared__ __align__(16) char smem[];
    char*  sAh = smem;                                // 8KB
    char*  sAl = smem + 8192;                         // 8KB
    char*  sBh = smem + 16384;                        // 4KB
    char*  sBl = smem + 20480;                        // 4KB
    float* sC  = (float*)(smem + 24576);              // [128][68]
    float* sP  = (float*)(smem + 59392);              // [U][64][65]
    float* sLS = (float*)(smem + 59392 + U * 64 * 65 * 4);
    float* sLD = sLS + U * 64;
    float* sAS = sLD + U * 64;
    float* sAD = sAS + 64;
    float* sBI = sAD + 64;

    const int tid  = threadIdx.x;
    const int wid  = tid >> 5;
    const int lane = tid & 31;
    const int row0 = blockIdx.y * 128;
    const int col0 = blockIdx.x * 64;

    // ---- GEMM global->smem mapping (16B chunks) ----
    const int arow0 = tid >> 2;
    const int ac    = tid & 3;
    const int arow1 = arow0 + 64;
    const uint32_t a_sts0 = STS_OFF(arow0, ac);
    const uint32_t a_sts1 = STS_OFF(arow1, ac);
    const uint32_t b_sts  = STS_OFF(arow0, ac);

    const bf16* gAh0 = Ah + (size_t)(row0 + arow0) * K + ac * 8;
    const bf16* gAh1 = Ah + (size_t)(row0 + arow1) * K + ac * 8;
    const bf16* gAl0 = Al + (size_t)(row0 + arow0) * K + ac * 8;
    const bf16* gAl1 = Al + (size_t)(row0 + arow1) * K + ac * 8;
    const bf16* gBh  = Bh + (size_t)(col0 + arow0) * K + ac * 8;
    const bf16* gBl  = Bl + (size_t)(col0 + arow0) * K + ac * 8;

    const int mr = (wid & 3) * 32;
    const int nb = (wid >> 2) * 32;
    const uint32_t sAh_b = smem_u32(sAh);
    const uint32_t sAl_b = smem_u32(sAl);
    const uint32_t sBh_b = smem_u32(sBh);
    const uint32_t sBl_b = smem_u32(sBl);

    const int rowlA = (lane & 7) + ((lane >> 3) & 1) * 8;
    const int chA   = (lane >> 4);
    const int rowlB = (lane & 7) + (lane >> 4) * 8;
    const int chB   = (lane >> 3) & 1;

    float acc[2][4][4];
    #pragma unroll
    for (int i = 0; i < 2; i++)
        #pragma unroll
        for (int j = 0; j < 4; j++)
            #pragma unroll
            for (int q = 0; q < 4; q++) acc[i][j][q] = 0.f;

    uint4 pa0h = *(const uint4*)gAh0;
    uint4 pa1h = *(const uint4*)gAh1;
    uint4 pa0l = *(const uint4*)gAl0;
    uint4 pa1l = *(const uint4*)gAl1;
    uint4 pbh  = *(const uint4*)gBh;
    uint4 pbl  = *(const uint4*)gBl;

    for (int t = 0; t < T; t++) {
        *(uint4*)(sAh + a_sts0) = pa0h;
        *(uint4*)(sAh + a_sts1) = pa1h;
        *(uint4*)(sAl + a_sts0) = pa0l;
        *(uint4*)(sAl + a_sts1) = pa1l;
        *(uint4*)(sBh + b_sts)  = pbh;
        *(uint4*)(sBl + b_sts)  = pbl;
        __syncthreads();

        if (t + 1 < T) {
            int ko = (t + 1) * 32;
            pa0h = *(const uint4*)(gAh0 + ko);
            pa1h = *(const uint4*)(gAh1 + ko);
            pa0l = *(const uint4*)(gAl0 + ko);
            pa1l = *(const uint4*)(gAl1 + ko);
            pbh  = *(const uint4*)(gBh + ko);
            pbl  = *(const uint4*)(gBl + ko);
        }

        #pragma unroll
        for (int kk = 0; kk < 2; kk++) {
            const int c0 = kk * 2;
            uint32_t fAh[2][4], fAl[2][4], fBh[2][4], fBl[2][4];
            #pragma unroll
            for (int sm = 0; sm < 2; sm++) {
                int r = mr + sm * 16 + rowlA;
                uint32_t off = r * 64 + (((c0 + chA) ^ ((r >> 1) & 3)) << 4);
                ldsm4(fAh[sm], sAh_b + off);
                ldsm4(fAl[sm], sAl_b + off);
            }
            #pragma unroll
            for (int tp = 0; tp < 2; tp++) {
                int r = nb + tp * 16 + rowlB;
                uint32_t off = r * 64 + (((c0 + chB) ^ ((r >> 1) & 3)) << 4);
                ldsm4(fBh[tp], sBh_b + off);
                ldsm4(fBl[tp], sBl_b + off);
            }
            #pragma unroll
            for (int sm = 0; sm < 2; sm++) {
                #pragma unroll
                for (int tn = 0; tn < 4; tn++) {
                    const int tp = tn >> 1, hf = (tn & 1) * 2;
                    const uint32_t bh[2] = {fBh[tp][hf], fBh[tp][hf + 1]};
                    const uint32_t bl[2] = {fBl[tp][hf], fBl[tp][hf + 1]};
                    mma16816(acc[sm][tn], fAh[sm], bh);
                    mma16816(acc[sm][tn], fAl[sm], bh);
                    mma16816(acc[sm][tn], fAh[sm], bl);
                }
            }
        }
        __syncthreads();
    }

    // ---- epilogue: fragments -> sC [128][68] ----
    {
        const int gid = lane >> 2;
        const int tig = lane & 3;
        #pragma unroll
        for (int sm = 0; sm < 2; sm++) {
            #pragma unroll
            for (int tn = 0; tn < 4; tn++) {
                int r = mr + sm * 16 + gid;
                int c = nb + tn * 8 + tig * 2;
                *(float2*)&sC[r * 68 + c] = make_float2(acc[sm][tn][0], acc[sm][tn][1]);
                *(float2*)&sC[(r + 8) * 68 + c] = make_float2(acc[sm][tn][2], acc[sm][tn][3]);
            }
        }
    }
    if (tid < 64) {
        sAS[tid] = a_src[col0 + tid];
        sAD[tid] = a_dst[col0 + tid];
        sBI[tid] = bias[col0 + tid];
    }
    __syncthreads();

    // ---- attention phase ----
    const int u  = tid / TU;
    const int ut = tid % TU;
    const int sb = u / HPT;              // sub graph block 0/1
    const int hl = u % HPT;              // head within tile
    const int cb = hl * CH;

    // ls/ld: one thread per node (threads ut<64 of each unit)
    if (ut < 64) {
        const int n = ut;
        const float* hp = &sC[(sb * 64 + n) * 68 + cb];
        float ls = 0.f, ld = 0.f;
        #pragma unroll
        for (int c = 0; c < CH; c++) {
            float hv = hp[c];
            ls += hv * sAS[cb + c];
            ld += hv * sAD[cb + c];
        }
        sLS[u * 64 + n] = ls;
        sLD[u * 64 + n] = ld;
    }
    __syncthreads();

    // softmax: warps of the unit stride rows
    {
        constexpr int NWU = TU / 32;
        const int lw = ut >> 5;
        const float ls0 = sLS[u * 64 + lane];
        const float ls1 = sLS[u * 64 + lane + 32];
        for (int i = lw; i < 64; i += NWU) {
            const float ldi = sLD[u * 64 + i];
            float v0 = ldi + ls0;
            float v1 = ldi + ls1;
            v0 = (v0 > 0.f) ? v0 : NEG_SLOPE * v0;
            v1 = (v1 > 0.f) ? v1 : NEG_SLOPE * v1;
            float mx = fmaxf(v0, v1);
            #pragma unroll
            for (int o = 16; o > 0; o >>= 1)
                mx = fmaxf(mx, __shfl_xor_sync(0xffffffffu, mx, o));
            float e0 = __expf(v0 - mx);
            float e1 = __expf(v1 - mx);
            float s = e0 + e1;
            #pragma unroll
            for (int o = 16; o > 0; o >>= 1)
                s += __shfl_xor_sync(0xffffffffu, s, o);
            float inv = 1.f / s;
            sP[(u * 64 + i) * 65 + lane]      = e0 * inv;
            sP[(u * 64 + i) * 65 + lane + 32] = e1 * inv;
        }
    }
    __syncthreads();

    // AV: out[i][c] = sum_j P[i][j] h[j][c]; thread covers 32 cols of row i
    {
        const int q    = ut >> 6;            // 0 (TU=64) or 0/1 (TU=128)
        const int i    = ut & 63;
        const int coff = cb + q * 32;
        ull avac[16];
        #pragma unroll
        for (int t = 0; t < 16; t++) avac[t] = 0ull;

        const float* prow = &sP[(u * 64 + i) * 65];
        #pragma unroll 8
        for (int j = 0; j < 64; j++) {
            float p = prow[j];
            ull pp = pack2(p, p);
            const ulonglong2* hrow = (const ulonglong2*)&sC[(sb * 64 + j) * 68 + coff];
            #pragma unroll
            for (int t = 0; t < 8; t++) {
                ulonglong2 hv = hrow[t];
                avac[2 * t]     = fma2(pp, hv.x, avac[2 * t]);
                avac[2 * t + 1] = fma2(pp, hv.y, avac[2 * t + 1]);
            }
        }
        float ob[32];
        #pragma unroll
        for (int t = 0; t < 16; t++) {
            float2 f = unpack2(avac[t]);
            ob[2 * t] = f.x; ob[2 * t + 1] = f.y;
        }
        #pragma unroll
        for (int k = 0; k < 32; k++) ob[k] += sBI[coff + k];

        if (OMODE == 1) {
            // split bf16 -> oh/ol, vectorized 8-bf16 stores
            const size_t m  = (size_t)(row0 + sb * 64 + i);
            const size_t go = m * HC12 + col0 + coff;
            uint uh[16], ulo[16];
            #pragma unroll
            for (int k = 0; k < 16; k++) {
                float v0 = ob[2 * k], v1 = ob[2 * k + 1];
                bf16 h0 = __float2bfloat16(v0);
                bf16 h1 = __float2bfloat16(v1);
                float r0 = v0 - __bfloat162float(h0);
                float r1 = v1 - __bfloat162float(h1);
                bf16 l0 = __float2bfloat16(r0);
                bf16 l1 = __float2bfloat16(r1);
                uh[k]  = (uint)__bfloat16_as_ushort(h0) | ((uint)__bfloat16_as_ushort(h1) << 16);
                ulo[k] = (uint)__bfloat16_as_ushort(l0) | ((uint)__bfloat16_as_ushort(l1) << 16);
            }
            #pragma unroll
            for (int k = 0; k < 4; k++) {
                *(uint4*)(oh + go + k * 8) = make_uint4(uh[4*k], uh[4*k+1], uh[4*k+2], uh[4*k+3]);
                *(uint4*)(ol + go + k * 8) = make_uint4(ulo[4*k], ulo[4*k+1], ulo[4*k+2], ulo[4*k+3]);
            }
        } else {
            // layer 3: stash rows, then mean over nodes
            __syncthreads();                 // P dead; reuse region as sO [U][64][33]
            float* sO = sP;
            #pragma unroll
            for (int k = 0; k < 32; k++)
                sO[(u * 64 + i) * 33 + k] = ob[k];
            __syncthreads();
            if (ut < 32) {
                const int c = ut;
                float s = 0.f;
                #pragma unroll 8
                for (int n = 0; n < 64; n++)
                    s += sO[(u * 64 + n) * 33 + c];
                const int g  = blockIdx.y * 2 + sb;
                const int hd = blockIdx.x * HPT + hl;
                outmean[(size_t)g * HC3 + hd * 32 + c] = s * (1.0f / 64.f);
            }
        }
    }
}

// ---------------------------------------------------------------------
extern "C" void kernel_launch(void* const* d_in, const int* in_sizes, int n_in,
                              void* d_out, int out_size) {
    const float* xs      = (const float*)d_in[0];
    const float* pos_enc = (const float*)d_in[1];
    const float* W1  = (const float*)d_in[2];
    const float* as1 = (const float*)d_in[3];
    const float* ad1 = (const float*)d_in[4];
    const float* b1  = (const float*)d_in[5];
    const float* W2  = (const float*)d_in[6];
    const float* as2 = (const float*)d_in[7];
    const float* ad2 = (const float*)d_in[8];
    const float* b2  = (const float*)d_in[9];
    const float* W3  = (const float*)d_in[10];
    const float* as3 = (const float*)d_in[11];
    const float* ad3 = (const float*)d_in[12];
    const float* b3  = (const float*)d_in[13];
    float* out = (float*)d_out;

    bf16 *a0h, *a0l, *a1h, *a1l, *a2h, *a2l;
    bf16 *w1h, *w1l, *w2h, *w2l, *w3h, *w3l;
    cudaGetSymbolAddress((void**)&a0h, g_a0h);
    cudaGetSymbolAddress((void**)&a0l, g_a0l);
    cudaGetSymbolAddress((void**)&a1h, g_a1h);
    cudaGetSymbolAddress((void**)&a1l, g_a1l);
    cudaGetSymbolAddress((void**)&a2h, g_a2h);
    cudaGetSymbolAddress((void**)&a2l, g_a2l);
    cudaGetSymbolAddress((void**)&w1h, g_w1h);
    cudaGetSymbolAddress((void**)&w1l, g_w1l);
    cudaGetSymbolAddress((void**)&w2h, g_w2h);
    cudaGetSymbolAddress((void**)&w2l, g_w2l);
    cudaGetSymbolAddress((void**)&w3h, g_w3h);
    cudaGetSymbolAddress((void**)&w3l, g_w3l);

    // dynamic smem sizes
    const int SME64 = 59392 + 2 * 64 * 65 * 4 + 2 * (2 * 64 * 4) + 3 * 256;  // 94464
    const int SME32 = 59392 + 4 * 64 * 65 * 4 + 2 * (4 * 64 * 4) + 3 * 256;  // 128768
    cudaFuncSetAttribute(gemm_attn<64, 64, 1>,
        cudaFuncAttributeMaxDynamicSharedMemorySize, SME64);
    cudaFuncSetAttribute(gemm_attn<512, 64, 1>,
        cudaFuncAttributeMaxDynamicSharedMemorySize, SME64);
    cudaFuncSetAttribute(gemm_attn<512, 32, 0>,
        cudaFuncAttributeMaxDynamicSharedMemorySize, SME32);

    // prep
    build_x0_split<<<(MROWS * 64 + 255) / 256, 256>>>(xs, pos_enc, a0h, a0l);
    prep_w<<<(512 * 64 + 255) / 256, 256>>>(W1, w1h, w1l, FIN, HC12, 64);
    prep_w<<<(512 * 512 + 255) / 256, 256>>>(W2, w2h, w2l, HC12, HC12, 512);
    prep_w<<<(256 * 512 + 255) / 256, 256>>>(W3, w3h, w3l, HC12, HC3, 512);

    // layer 1: x0[.,64] @ W1 -> attn -> a1 (split bf16)
    gemm_attn<64, 64, 1><<<dim3(HEADS, MROWS / 128), 256, SME64>>>(
        a0h, a0l, w1h, w1l, as1, ad1, b1, a1h, a1l, nullptr);
    // layer 2: a1 @ W2 -> attn -> a2
    gemm_attn<512, 64, 1><<<dim3(HEADS, MROWS / 128), 256, SME64>>>(
        a1h, a1l, w2h, w2l, as2, ad2, b2, a2h, a2l, nullptr);
    // layer 3: a2 @ W3 -> attn -> mean -> out
    gemm_attn<512, 32, 0><<<dim3(HC3 / 64, MROWS / 128), 256, SME32>>>(
        a2h, a2l, w3h, w3l, as3, ad3, b3, nullptr, nullptr, out);
}

// round 6
// speedup vs baseline: 5.0974x; 1.1287x over previous
#include <cuda_runtime.h>
#include <cuda_bf16.h>
#include <cstdint>

// Problem constants
#define BS        8
#define RDIM      256
#define NBLK      (BS * RDIM)      // 2048
#define NODES     64
#define MROWS     (NBLK * NODES)   // 131072
#define ENC       31
#define FIN       32
#define HEADS     8
#define HID       64
#define OUTC      32
#define HC12      (HEADS * HID)    // 512
#define HC3       (HEADS * OUTC)   // 256
#define NEG_SLOPE 0.2f

typedef unsigned long long ull;
typedef __nv_bfloat16 bf16;

// ---------------- packed fp32x2 helpers ----------------
__device__ __forceinline__ ull pack2(float x, float y) {
    ull r; asm("mov.b64 %0, {%1, %2};" : "=l"(r) : "f"(x), "f"(y)); return r;
}
__device__ __forceinline__ ull fma2(ull a, ull b, ull c) {
    ull d; asm("fma.rn.f32x2 %0, %1, %2, %3;" : "=l"(d) : "l"(a), "l"(b), "l"(c)); return d;
}
__device__ __forceinline__ float2 unpack2(ull v) {
    float2 f; asm("mov.b64 {%0, %1}, %2;" : "=f"(f.x), "=f"(f.y) : "l"(v)); return f;
}
__device__ __forceinline__ uint32_t smem_u32(const void* p) {
    uint32_t a;
    asm("{ .reg .u64 t; cvta.to.shared.u64 t, %1; cvt.u32.u64 %0, t; }" : "=r"(a) : "l"(p));
    return a;
}

// ---------------- mma.sync / ldmatrix / cp.async ----------------
__device__ __forceinline__ void ldsm4(uint32_t* r, uint32_t addr) {
    asm volatile("ldmatrix.sync.aligned.m8n8.x4.shared.b16 {%0,%1,%2,%3}, [%4];"
        : "=r"(r[0]), "=r"(r[1]), "=r"(r[2]), "=r"(r[3]) : "r"(addr));
}
__device__ __forceinline__ void mma16816(float* d, const uint32_t* a, const uint32_t* b) {
    asm volatile(
        "mma.sync.aligned.m16n8k16.row.col.f32.bf16.bf16.f32 "
        "{%0,%1,%2,%3}, {%4,%5,%6,%7}, {%8,%9}, {%0,%1,%2,%3};"
        : "+f"(d[0]), "+f"(d[1]), "+f"(d[2]), "+f"(d[3])
        : "r"(a[0]), "r"(a[1]), "r"(a[2]), "r"(a[3]), "r"(b[0]), "r"(b[1]));
}
__device__ __forceinline__ void cp16(uint32_t dst, const void* src) {
    asm volatile("cp.async.cg.shared.global [%0], [%1], 16;" :: "r"(dst), "l"(src));
}
#define CP_COMMIT() asm volatile("cp.async.commit_group;" ::: "memory")
#define CP_WAIT(n)  asm volatile("cp.async.wait_group %0;" :: "n"(n) : "memory")

// ---------------- device scratch ----------------
__device__ bf16 g_a0h[(size_t)MROWS * 64],  g_a0l[(size_t)MROWS * 64];
__device__ bf16 g_a1h[(size_t)MROWS * HC12], g_a1l[(size_t)MROWS * HC12];
__device__ bf16 g_a2h[(size_t)MROWS * HC12], g_a2l[(size_t)MROWS * HC12];
__device__ bf16 g_w1h[512 * 64],  g_w1l[512 * 64];
__device__ bf16 g_w2h[512 * 512], g_w2l[512 * 512];
__device__ bf16 g_w3h[256 * 512], g_w3l[256 * 512];

// ---------------- prep kernels ----------------
__global__ void build_x0_split(const float* __restrict__ xs,
                               const float* __restrict__ pos_enc,
                               bf16* __restrict__ ah, bf16* __restrict__ al) {
    int idx = blockIdx.x * blockDim.x + threadIdx.x;   // MROWS*64
    if (idx >= MROWS * 64) return;
    int m = idx >> 6;
    int f = idx & 63;
    float v = 0.f;
    if (f == 0) v = xs[m];
    else if (f < FIN) {
        int b = m / (RDIM * NODES);
        int n = m % NODES;
        v = pos_enc[(b * NODES + n) * ENC + (f - 1)];
    }
    bf16 h = __float2bfloat16(v);
    ah[idx] = h;
    al[idx] = __float2bfloat16(v - __bfloat162float(h));
}

// W [Ksrc, N] -> Wt_hi/lo [N, Kpad] (transposed, zero-padded, split)
__global__ void prep_w(const float* __restrict__ W, bf16* __restrict__ th,
                       bf16* __restrict__ tl, int Ksrc, int N, int Kpad) {
    int idx = blockIdx.x * blockDim.x + threadIdx.x;
    if (idx >= N * Kpad) return;
    int n = idx / Kpad, k = idx % Kpad;
    float v = (k < Ksrc) ? W[(size_t)k * N + n] : 0.f;
    bf16 h = __float2bfloat16(v);
    th[idx] = h;
    tl[idx] = __float2bfloat16(v - __bfloat162float(h));
}

// ---------------- fused GEMM (split-bf16 x3 HMMA) + GAT attention ----------------
// Tile 128x64. 2-stage cp.async pipeline; sC aliases the stage buffers.
// Dynamic smem layout:
//   [0, 49152)  : stage s at s*24576 {Ah 8K | Al 8K | Bh 4K | Bl 4K}
//   sC (float[128][68], 34816 B) aliases offset 0 (used after mainloop)
//   [49152, ..) : sP [U][64][65] | sLS [U][64] | sLD [U][64] | sAS/sAD/sBI [64]
#define STAGE 24576
#define STS_OFF(row, c) ((row) * 64 + ((((c) ^ (((row) >> 1) & 3))) << 4))

template<int K, int CH, int OMODE>
__global__ __launch_bounds__(256) void gemm_attn(
    const bf16* __restrict__ Ah, const bf16* __restrict__ Al,
    const bf16* __restrict__ Bh, const bf16* __restrict__ Bl,
    const float* __restrict__ a_src, const float* __restrict__ a_dst,
    const float* __restrict__ bias,
    bf16* __restrict__ oh, bf16* __restrict__ ol,
    float* __restrict__ outmean) {
    constexpr int HPT = 64 / CH;     // heads per tile
    constexpr int U   = 2 * HPT;     // attention units per CTA
    constexpr int TU  = 256 / U;     // threads per unit
    constexpr int T   = K / 32;

    extern __shared__ __align__(16) char smem[];
    float* sC  = (float*)smem;                        // [128][68] (alias)
    float* sP  = (float*)(smem + 49152);              // [U][64][65]
    float* sLS = (float*)(smem + 49152 + U * 64 * 65 * 4);
    float* sLD = sLS + U * 64;
    float* sAS = sLD + U * 64;
    float* sAD = sAS + 64;
    float* sBI = sAD + 64;

    const int tid  = threadIdx.x;
    const int wid  = tid >> 5;
    const int lane = tid & 31;
    const int row0 = blockIdx.y * 128;
    const int col0 = blockIdx.x * 64;
    const uint32_t smem_base = smem_u32(smem);

    // ---- GEMM global->smem mapping (16B chunks) ----
    const int arow0 = tid >> 2;
    const int ac    = tid & 3;
    const uint32_t a_sts0 = STS_OFF(arow0, ac);
    const uint32_t a_sts1 = STS_OFF(arow0 + 64, ac);
    const uint32_t b_sts  = STS_OFF(arow0, ac);

    const bf16* gAh0 = Ah + (size_t)(row0 + arow0) * K + ac * 8;
    const bf16* gAh1 = gAh0 + (size_t)64 * K;
    const bf16* gAl0 = Al + (size_t)(row0 + arow0) * K + ac * 8;
    const bf16* gAl1 = gAl0 + (size_t)64 * K;
    const bf16* gBh  = Bh + (size_t)(col0 + arow0) * K + ac * 8;
    const bf16* gBl  = Bl + (size_t)(col0 + arow0) * K + ac * 8;

    const int mr = (wid & 3) * 32;
    const int nb = (wid >> 2) * 32;
    const int rowlA = (lane & 7) + ((lane >> 3) & 1) * 8;
    const int chA   = (lane >> 4);
    const int rowlB = (lane & 7) + (lane >> 4) * 8;
    const int chB   = (lane >> 3) & 1;

    float acc[2][4][4];
    #pragma unroll
    for (int i = 0; i < 2; i++)
        #pragma unroll
        for (int j = 0; j < 4; j++)
            #pragma unroll
            for (int q = 0; q < 4; q++) acc[i][j][q] = 0.f;

    auto issue_stage = [&](int s, int k0) {
        const uint32_t sb = smem_base + s * STAGE;
        cp16(sb + a_sts0, gAh0 + k0);
        cp16(sb + a_sts1, gAh1 + k0);
        cp16(sb + 8192 + a_sts0, gAl0 + k0);
        cp16(sb + 8192 + a_sts1, gAl1 + k0);
        cp16(sb + 16384 + b_sts, gBh + k0);
        cp16(sb + 20480 + b_sts, gBl + k0);
    };

    issue_stage(0, 0);
    CP_COMMIT();

    #pragma unroll 1
    for (int t = 0; t < T; t++) {
        __syncthreads();              // everyone done reading buf[(t+1)&1]
        if (t + 1 < T) {
            issue_stage((t + 1) & 1, (t + 1) * 32);
            CP_COMMIT();
            CP_WAIT(1);               // group t complete; t+1 in flight
        } else {
            CP_WAIT(0);
        }
        __syncthreads();              // stage t visible to all

        const uint32_t stg = smem_base + (t & 1) * STAGE;
        #pragma unroll
        for (int kk = 0; kk < 2; kk++) {
            const int c0 = kk * 2;
            uint32_t fAh[2][4], fAl[2][4], fBh[2][4], fBl[2][4];
            #pragma unroll
            for (int sm = 0; sm < 2; sm++) {
                int r = mr + sm * 16 + rowlA;
                uint32_t off = r * 64 + (((c0 + chA) ^ ((r >> 1) & 3)) << 4);
                ldsm4(fAh[sm], stg + off);
                ldsm4(fAl[sm], stg + 8192 + off);
            }
            #pragma unroll
            for (int tp = 0; tp < 2; tp++) {
                int r = nb + tp * 16 + rowlB;
                uint32_t off = r * 64 + (((c0 + chB) ^ ((r >> 1) & 3)) << 4);
                ldsm4(fBh[tp], stg + 16384 + off);
                ldsm4(fBl[tp], stg + 20480 + off);
            }
            #pragma unroll
            for (int sm = 0; sm < 2; sm++) {
                #pragma unroll
                for (int tn = 0; tn < 4; tn++) {
                    const int tp = tn >> 1, hf = (tn & 1) * 2;
                    const uint32_t bh[2] = {fBh[tp][hf], fBh[tp][hf + 1]};
                    const uint32_t bl[2] = {fBl[tp][hf], fBl[tp][hf + 1]};
                    mma16816(acc[sm][tn], fAh[sm], bh);
                    mma16816(acc[sm][tn], fAl[sm], bh);
                    mma16816(acc[sm][tn], fAh[sm], bl);
                }
            }
        }
    }
    __syncthreads();                  // all ldsm reads done; safe to alias sC

    // ---- epilogue: fragments -> sC [128][68] ----
    {
        const int gid = lane >> 2;
        const int tig = lane & 3;
        #pragma unroll
        for (int sm = 0; sm < 2; sm++) {
            #pragma unroll
            for (int tn = 0; tn < 4; tn++) {
                int r = mr + sm * 16 + gid;
                int c = nb + tn * 8 + tig * 2;
                *(float2*)&sC[r * 68 + c] = make_float2(acc[sm][tn][0], acc[sm][tn][1]);
                *(float2*)&sC[(r + 8) * 68 + c] = make_float2(acc[sm][tn][2], acc[sm][tn][3]);
            }
        }
    }
    if (tid < 64) {
        sAS[tid] = a_src[col0 + tid];
        sAD[tid] = a_dst[col0 + tid];
        sBI[tid] = bias[col0 + tid];
    }
    __syncthreads();

    // ---- attention phase ----
    const int u  = tid / TU;
    const int ut = tid % TU;
    const int sb = u / HPT;              // sub graph block 0/1
    const int hl = u % HPT;              // head within tile
    const int cb = hl * CH;

    if (ut < 64) {
        const int n = ut;
        const float* hp = &sC[(sb * 64 + n) * 68 + cb];
        float ls = 0.f, ld = 0.f;
        #pragma unroll
        for (int c = 0; c < CH; c++) {
            float hv = hp[c];
            ls += hv * sAS[cb + c];
            ld += hv * sAD[cb + c];
        }
        sLS[u * 64 + n] = ls;
        sLD[u * 64 + n] = ld;
    }
    __syncthreads();

    {   // softmax: warps of the unit stride rows
        constexpr int NWU = TU / 32;
        const int lw = ut >> 5;
        const float ls0 = sLS[u * 64 + lane];
        const float ls1 = sLS[u * 64 + lane + 32];
        for (int i = lw; i < 64; i += NWU) {
            const float ldi = sLD[u * 64 + i];
            float v0 = ldi + ls0;
            float v1 = ldi + ls1;
            v0 = (v0 > 0.f) ? v0 : NEG_SLOPE * v0;
            v1 = (v1 > 0.f) ? v1 : NEG_SLOPE * v1;
            float mx = fmaxf(v0, v1);
            #pragma unroll
            for (int o = 16; o > 0; o >>= 1)
                mx = fmaxf(mx, __shfl_xor_sync(0xffffffffu, mx, o));
            float e0 = __expf(v0 - mx);
            float e1 = __expf(v1 - mx);
            float s = e0 + e1;
            #pragma unroll
            for (int o = 16; o > 0; o >>= 1)
                s += __shfl_xor_sync(0xffffffffu, s, o);
            float inv = 1.f / s;
            sP[(u * 64 + i) * 65 + lane]      = e0 * inv;
            sP[(u * 64 + i) * 65 + lane + 32] = e1 * inv;
        }
    }
    __syncthreads();

    {   // AV: out[i][c] = sum_j P[i][j] h[j][c]; thread covers 32 cols of row i
        const int q    = ut >> 6;
        const int i    = ut & 63;
        const int coff = cb + q * 32;
        ull avac[16];
        #pragma unroll
        for (int t = 0; t < 16; t++) avac[t] = 0ull;

        const float* prow = &sP[(u * 64 + i) * 65];
        #pragma unroll 8
        for (int j = 0; j < 64; j++) {
            float p = prow[j];
            ull pp = pack2(p, p);
            const ulonglong2* hrow = (const ulonglong2*)&sC[(sb * 64 + j) * 68 + coff];
            #pragma unroll
            for (int t = 0; t < 8; t++) {
                ulonglong2 hv = hrow[t];
                avac[2 * t]     = fma2(pp, hv.x, avac[2 * t]);
                avac[2 * t + 1] = fma2(pp, hv.y, avac[2 * t + 1]);
            }
        }
        float ob[32];
        #pragma unroll
        for (int t = 0; t < 16; t++) {
            float2 f = unpack2(avac[t]);
            ob[2 * t] = f.x; ob[2 * t + 1] = f.y;
        }
        #pragma unroll
        for (int k = 0; k < 32; k++) ob[k] += sBI[coff + k];

        if (OMODE == 1) {
            const size_t m  = (size_t)(row0 + sb * 64 + i);
            const size_t go = m * HC12 + col0 + coff;
            uint uh[16], ulo[16];
            #pragma unroll
            for (int k = 0; k < 16; k++) {
                float v0 = ob[2 * k], v1 = ob[2 * k + 1];
                bf16 h0 = __float2bfloat16(v0);
                bf16 h1 = __float2bfloat16(v1);
                float r0 = v0 - __bfloat162float(h0);
                float r1 = v1 - __bfloat162float(h1);
                bf16 l0 = __float2bfloat16(r0);
                bf16 l1 = __float2bfloat16(r1);
                uh[k]  = (uint)__bfloat16_as_ushort(h0) | ((uint)__bfloat16_as_ushort(h1) << 16);
                ulo[k] = (uint)__bfloat16_as_ushort(l0) | ((uint)__bfloat16_as_ushort(l1) << 16);
            }
            #pragma unroll
            for (int k = 0; k < 4; k++) {
                *(uint4*)(oh + go + k * 8) = make_uint4(uh[4*k], uh[4*k+1], uh[4*k+2], uh[4*k+3]);
                *(uint4*)(ol + go + k * 8) = make_uint4(ulo[4*k], ulo[4*k+1], ulo[4*k+2], ulo[4*k+3]);
            }
        } else {
            __syncthreads();                 // P dead; reuse as sO [U][64][33]
            float* sO = sP;
            #pragma unroll
            for (int k = 0; k < 32; k++)
                sO[(u * 64 + i) * 33 + k] = ob[k];
            __syncthreads();
            if (ut < 32) {
                const int c = ut;
                float s = 0.f;
                #pragma unroll 8
                for (int n = 0; n < 64; n++)
                    s += sO[(u * 64 + n) * 33 + c];
                const int g  = blockIdx.y * 2 + sb;
                const int hd = blockIdx.x * HPT + hl;
                outmean[(size_t)g * HC3 + hd * 32 + c] = s * (1.0f / 64.f);
            }
        }
    }
}

// ---------------------------------------------------------------------
extern "C" void kernel_launch(void* const* d_in, const int* in_sizes, int n_in,
                              void* d_out, int out_size) {
    const float* xs      = (const float*)d_in[0];
    const float* pos_enc = (const float*)d_in[1];
    const float* W1  = (const float*)d_in[2];
    const float* as1 = (const float*)d_in[3];
    const float* ad1 = (const float*)d_in[4];
    const float* b1  = (const float*)d_in[5];
    const float* W2  = (const float*)d_in[6];
    const float* as2 = (const float*)d_in[7];
    const float* ad2 = (const float*)d_in[8];
    const float* b2  = (const float*)d_in[9];
    const float* W3  = (const float*)d_in[10];
    const float* as3 = (const float*)d_in[11];
    const float* ad3 = (const float*)d_in[12];
    const float* b3  = (const float*)d_in[13];
    float* out = (float*)d_out;

    bf16 *a0h, *a0l, *a1h, *a1l, *a2h, *a2l;
    bf16 *w1h, *w1l, *w2h, *w2l, *w3h, *w3l;
    cudaGetSymbolAddress((void**)&a0h, g_a0h);
    cudaGetSymbolAddress((void**)&a0l, g_a0l);
    cudaGetSymbolAddress((void**)&a1h, g_a1h);
    cudaGetSymbolAddress((void**)&a1l, g_a1l);
    cudaGetSymbolAddress((void**)&a2h, g_a2h);
    cudaGetSymbolAddress((void**)&a2l, g_a2l);
    cudaGetSymbolAddress((void**)&w1h, g_w1h);
    cudaGetSymbolAddress((void**)&w1l, g_w1l);
    cudaGetSymbolAddress((void**)&w2h, g_w2h);
    cudaGetSymbolAddress((void**)&w2l, g_w2l);
    cudaGetSymbolAddress((void**)&w3h, g_w3h);
    cudaGetSymbolAddress((void**)&w3l, g_w3l);

    // dynamic smem sizes
    const int SME64 = 49152 + 2 * 64 * 65 * 4 + 2 * (2 * 64 * 4) + 3 * 256;  // 84224
    const int SME32 = 49152 + 4 * 64 * 65 * 4 + 2 * (4 * 64 * 4) + 3 * 256;  // 118528
    cudaFuncSetAttribute(gemm_attn<64, 64, 1>,
        cudaFuncAttributeMaxDynamicSharedMemorySize, SME64);
    cudaFuncSetAttribute(gemm_attn<512, 64, 1>,
        cudaFuncAttributeMaxDynamicSharedMemorySize, SME64);
    cudaFuncSetAttribute(gemm_attn<512, 32, 0>,
        cudaFuncAttributeMaxDynamicSharedMemorySize, SME32);

    // prep
    build_x0_split<<<(MROWS * 64 + 255) / 256, 256>>>(xs, pos_enc, a0h, a0l);
    prep_w<<<(512 * 64 + 255) / 256, 256>>>(W1, w1h, w1l, FIN, HC12, 64);
    prep_w<<<(512 * 512 + 255) / 256, 256>>>(W2, w2h, w2l, HC12, HC12, 512);
    prep_w<<<(256 * 512 + 255) / 256, 256>>>(W3, w3h, w3l, HC12, HC3, 512);

    // layer 1
    gemm_attn<64, 64, 1><<<dim3(HEADS, MROWS / 128), 256, SME64>>>(
        a0h, a0l, w1h, w1l, as1, ad1, b1, a1h, a1l, nullptr);
    // layer 2
    gemm_attn<512, 64, 1><<<dim3(HEADS, MROWS / 128), 256, SME64>>>(
        a1h, a1l, w2h, w2l, as2, ad2, b2, a2h, a2l, nullptr);
    // layer 3
    gemm_attn<512, 32, 0><<<dim3(HC3 / 64, MROWS / 128), 256, SME32>>>(
        a2h, a2l, w3h, w3l, as3, ad3, b3, nullptr, nullptr, out);
}